// round 11
// baseline (speedup 1.0000x reference)
#include <cuda_runtime.h>
#include <cuda_fp16.h>
#include <math.h>
#include <stdint.h>

#define B 8
#define L1 384
#define L2 384
#define H 128
#define H2 256
#define H4 512

// ---- scratch (allocation-free: __device__ globals) ----
__device__ float d_xp[B * L1 * H];
__device__ float d_yp[B * L2 * H];
__device__ float d_s [B * L1 * L2];
__device__ float d_ct[B * L1 * H];
__device__ float d_gx[B * L1 * H4];

__device__ __forceinline__ float tanh_fast(float x) {
    float y;
    asm("tanh.approx.f32 %0, %1;" : "=f"(y) : "f"(x));
    return y;
}
__device__ __forceinline__ float sigmoid_acc(float x) {
    x = fminf(fmaxf(x, -30.f), 30.f);
    return 1.f / (1.f + __expf(-x));
}
__device__ __forceinline__ float tanh_acc(float x) {
    x = fminf(fmaxf(x, -15.f), 15.f);
    float e = __expf(-2.f * x);
    return (1.f - e) / (1.f + e);
}

// m16n8k16 f16xf16+f32 HMMA (baseline PTX, works on compute_103)
__device__ __forceinline__ void mma16816(float* d, const uint32_t* a, const uint32_t* b) {
    asm volatile(
        "mma.sync.aligned.m16n8k16.row.col.f32.f16.f16.f32 "
        "{%0,%1,%2,%3}, {%4,%5,%6,%7}, {%8,%9}, {%0,%1,%2,%3};\n"
        : "+f"(d[0]), "+f"(d[1]), "+f"(d[2]), "+f"(d[3])
        : "r"(a[0]), "r"(a[1]), "r"(a[2]), "r"(a[3]), "r"(b[0]), "r"(b[1]));
}

// ============================================================
// Kernel A: row projections
// ============================================================
__global__ void k_proj(const float* __restrict__ x, const float* __restrict__ y,
                       const float* __restrict__ Wup, const float* __restrict__ bup,
                       const float* __restrict__ Wq,  const float* __restrict__ bq,
                       const float* __restrict__ bvp)
{
    int row = blockIdx.x;
    int o   = threadIdx.x;
    __shared__ float4 in4[H / 4];

    const float* in; const float* W; float bias; float* out;
    if (row < B * L1) {
        in = x + (size_t)row * H;  W = Wup;  bias = bup[o];           out = d_xp + (size_t)row * H;
    } else {
        int r = row - B * L1;
        in = y + (size_t)r * H;    W = Wq;   bias = bq[o] + bvp[o];   out = d_yp + (size_t)r * H;
    }
    if (o < H / 4) in4[o] = ((const float4*)in)[o];
    __syncthreads();

    const float4* W4 = (const float4*)(W + (size_t)o * H);
    float acc = bias;
#pragma unroll
    for (int k = 0; k < H / 4; k++) {
        float4 w = W4[k];
        float4 v = in4[k];
        acc += w.x * v.x + w.y * v.y + w.z * v.z + w.w * v.w;
    }
    out[o] = acc;
}

// ============================================================
// Kernel B: additive attention scores (MUFU-bound)
// ============================================================
__global__ void k_scores(const unsigned char* __restrict__ xmask,
                         const unsigned char* __restrict__ ymask,
                         const float* __restrict__ Vw, const float* __restrict__ Vb)
{
    int b  = blockIdx.z;
    int t0 = blockIdx.y * 32;
    int j0 = blockIdx.x * 32;

    __shared__ float4 xs[32 * 32];
    __shared__ float4 ys[32 * 33];
    __shared__ float4 vs[32];

    int tid = threadIdx.y * 32 + threadIdx.x;
    for (int i = tid; i < 32 * 32; i += 256) {
        int r = i >> 5, k = i & 31;
        xs[r * 32 + k] = ((const float4*)(d_xp + (size_t)((b * L1) + t0 + r) * H))[k];
        ys[r * 33 + k] = ((const float4*)(d_yp + (size_t)((b * L2) + j0 + r) * H))[k];
    }
    if (tid < 32) vs[tid] = ((const float4*)Vw)[tid];
    __syncthreads();

    int j = threadIdx.x;
    float acc[4] = {0.f, 0.f, 0.f, 0.f};

#pragma unroll 4
    for (int k = 0; k < 32; k++) {
        float4 yv = ys[j * 33 + k];
        float4 v  = vs[k];
#pragma unroll
        for (int i = 0; i < 4; i++) {
            float4 xv = xs[(threadIdx.y + i * 8) * 32 + k];
            acc[i] += v.x * tanh_fast(xv.x + yv.x);
            acc[i] += v.y * tanh_fast(xv.y + yv.y);
            acc[i] += v.z * tanh_fast(xv.z + yv.z);
            acc[i] += v.w * tanh_fast(xv.w + yv.w);
        }
    }

    bool  ymb = ymask[b * L2 + j0 + j] != 0;
    float ymv = ymb ? 0.f : 1.f;
    float vb  = Vb[0];
    const float NEG_INF = __int_as_float(0xff800000);
#pragma unroll
    for (int i = 0; i < 4; i++) {
        int t   = t0 + threadIdx.y + i * 8;
        float xm = (xmask[b * L1 + t] != 0) ? 0.f : 1.f;
        float s  = (acc[i] + vb) * (xm * ymv);
        if (ymb) s = NEG_INF;
        d_s[(size_t)((b * L1) + t) * L2 + j0 + j] = s;
    }
}

// ============================================================
// Kernel C: softmax over j
// ============================================================
__global__ void k_softmax()
{
    int row = blockIdx.x;
    float* s = d_s + (size_t)row * L2;
    int tid = threadIdx.x;   // 128

    float v[3];
    float m = -INFINITY;
#pragma unroll
    for (int i = 0; i < 3; i++) { v[i] = s[tid + i * 128]; m = fmaxf(m, v[i]); }

    __shared__ float red[4];
#pragma unroll
    for (int o = 16; o > 0; o >>= 1) m = fmaxf(m, __shfl_xor_sync(~0u, m, o));
    if ((tid & 31) == 0) red[tid >> 5] = m;
    __syncthreads();
    m = fmaxf(fmaxf(red[0], red[1]), fmaxf(red[2], red[3]));

    float sum = 0.f;
#pragma unroll
    for (int i = 0; i < 3; i++) { v[i] = __expf(v[i] - m); sum += v[i]; }
#pragma unroll
    for (int o = 16; o > 0; o >>= 1) sum += __shfl_xor_sync(~0u, sum, o);
    __shared__ float red2[4];
    if ((tid & 31) == 0) red2[tid >> 5] = sum;
    __syncthreads();
    sum = red2[0] + red2[1] + red2[2] + red2[3];

    float inv = 1.0f / sum;
#pragma unroll
    for (int i = 0; i < 3; i++) s[tid + i * 128] = v[i] * inv;
}

// ============================================================
// Kernel D: ct = alpha @ y
// ============================================================
#define NCHUNK (L2 / 32)
__global__ void k_ctx(const float* __restrict__ y)
{
    int b  = blockIdx.y;
    int t0 = blockIdx.x * 16;
    __shared__ __align__(16) float ysm[32 * 128];
    __shared__ float alph[16 * 32];

    int tid = threadIdx.x;       // 256
    int h   = tid & 127;
    int tg  = tid >> 7;
    float acc[8] = {0.f, 0.f, 0.f, 0.f, 0.f, 0.f, 0.f, 0.f};

    const float4* y4 = (const float4*)(y + (size_t)b * L2 * H);
    const float*  sp = d_s + (size_t)(b * L1 + t0) * L2;

    float4 ybuf[4];
    float  abuf[2];
#pragma unroll
    for (int q = 0; q < 4; q++) ybuf[q] = y4[tid + 256 * q];
#pragma unroll
    for (int q = 0; q < 2; q++) {
        int i = tid + 256 * q;
        abuf[q] = sp[(size_t)(i >> 5) * L2 + (i & 31)];
    }

    for (int c = 0; c < NCHUNK; c++) {
        __syncthreads();
#pragma unroll
        for (int q = 0; q < 4; q++) ((float4*)ysm)[tid + 256 * q] = ybuf[q];
#pragma unroll
        for (int q = 0; q < 2; q++) alph[tid + 256 * q] = abuf[q];
        __syncthreads();

        if (c + 1 < NCHUNK) {
#pragma unroll
            for (int q = 0; q < 4; q++) ybuf[q] = y4[(c + 1) * 1024 + tid + 256 * q];
#pragma unroll
            for (int q = 0; q < 2; q++) {
                int i = tid + 256 * q;
                abuf[q] = sp[(size_t)(i >> 5) * L2 + (c + 1) * 32 + (i & 31)];
            }
        }

#pragma unroll 8
        for (int jj = 0; jj < 32; jj++) {
            float yv = ysm[jj * 128 + h];
#pragma unroll
            for (int i = 0; i < 8; i++)
                acc[i] += alph[(tg * 8 + i) * 32 + jj] * yv;
        }
    }
#pragma unroll
    for (int i = 0; i < 8; i++)
        d_ct[(size_t)((b * L1) + t0 + tg * 8 + i) * H + h] = acc[i];
}

// ============================================================
// Kernel E (fused): li = sigmoid([x,ct]@Wg^T+bg)*[x,ct] in SMEM,
// then gx = li @ W_ih^T + (b_ih+b_hh).
// ============================================================
__global__ void k_gates(const float* __restrict__ x,
                        const float* __restrict__ Wg,  const float* __restrict__ bg,
                        const float* __restrict__ Wih, const float* __restrict__ bih,
                        const float* __restrict__ bhh)
{
    int r0 = blockIdx.x * 32;
    int c  = threadIdx.x;                          // 256
    __shared__ __align__(16) float ms [32 * H2];
    __shared__ __align__(16) float lis[32 * H2];

    for (int i = c; i < 32 * H2; i += 256) {
        int r = i >> 8, k = i & 255;
        ms[i] = (k < H) ? x[(size_t)(r0 + r) * H + k]
                        : d_ct[(size_t)(r0 + r) * H + (k - H)];
    }
    __syncthreads();

    {
        float acc[32];
#pragma unroll
        for (int r = 0; r < 32; r++) acc[r] = 0.f;

        const float4* W4  = (const float4*)(Wg + (size_t)c * H2);
        const float4* ms4 = (const float4*)ms;
        for (int k = 0; k < H2 / 4; k++) {
            float4 w = W4[k];
#pragma unroll
            for (int r = 0; r < 32; r++) {
                float4 m = ms4[r * (H2 / 4) + k];
                acc[r] += w.x * m.x + w.y * m.y + w.z * m.z + w.w * m.w;
            }
        }
        float bias = bg[c];
#pragma unroll
        for (int r = 0; r < 32; r++) {
            float g = 1.0f / (1.0f + __expf(-(acc[r] + bias)));
            lis[r * H2 + c] = g * ms[r * H2 + c];
        }
    }
    __syncthreads();

    {
        float acc0[32], acc1[32];
#pragma unroll
        for (int r = 0; r < 32; r++) { acc0[r] = 0.f; acc1[r] = 0.f; }

        const float4* Wa  = (const float4*)(Wih + (size_t)c * H2);
        const float4* Wb  = (const float4*)(Wih + (size_t)(c + 256) * H2);
        const float4* li4 = (const float4*)lis;
        for (int k = 0; k < H2 / 4; k++) {
            float4 wa = Wa[k];
            float4 wb = Wb[k];
#pragma unroll
            for (int r = 0; r < 32; r++) {
                float4 m = li4[r * (H2 / 4) + k];
                acc0[r] += wa.x * m.x + wa.y * m.y + wa.z * m.z + wa.w * m.w;
                acc1[r] += wb.x * m.x + wb.y * m.y + wb.z * m.z + wb.w * m.w;
            }
        }
        float bias0 = bih[c] + bhh[c];
        float bias1 = bih[c + 256] + bhh[c + 256];
#pragma unroll
        for (int r = 0; r < 32; r++) {
            d_gx[(size_t)(r0 + r) * H4 + c]       = acc0[r] + bias0;
            d_gx[(size_t)(r0 + r) * H4 + c + 256] = acc1[r] + bias1;
        }
    }
}

// ============================================================
// Kernel F: HMMA LSTM. One block per batch, 512 threads (16 warps).
// gates[512] = W_hh[512,128] @ h (replicated to 8 N-cols) via
// mma.sync.m16n8k16: warp w owns gate rows [w*32, w*32+32) as 2 m-tiles;
// A (W_hh) fragments live in registers permanently (64 b32/thread);
// B fragments built per step from fp16 hs[] (broadcast LDS.32);
// fp32 accumulation inside the tensor pipe. lane%4==0 threads hold
// d0/d2 = gate preacts, add prefetched gx, activate into gs[].
// Cell phase (tid<128) + 2 barriers = R7's measured-best structure.
// ============================================================
__global__ void __launch_bounds__(512, 1)
k_lstm(const float* __restrict__ Whh, float* __restrict__ out)
{
    __shared__ __align__(8) __half hs[H];
    __shared__ float gs[H4];

    int b    = blockIdx.x;
    int tid  = threadIdx.x;
    int w    = tid >> 5;
    int lane = tid & 31;
    int qr   = lane >> 2;        // 0..7
    int qc   = (lane & 3) * 2;   // 0,2,4,6

    // ---- one-time: A fragments (W_hh) into registers, PTX m16n8k16 mapping ----
    uint32_t afr[2][8][4];
#pragma unroll
    for (int t = 0; t < 2; t++) {
        int r0 = w * 32 + t * 16 + qr;
#pragma unroll
        for (int kt = 0; kt < 8; kt++) {
            int c0 = kt * 16 + qc;
            float2 x0 = *(const float2*)(Whh + (size_t)r0 * H + c0);
            float2 x1 = *(const float2*)(Whh + (size_t)(r0 + 8) * H + c0);
            float2 x2 = *(const float2*)(Whh + (size_t)r0 * H + c0 + 8);
            float2 x3 = *(const float2*)(Whh + (size_t)(r0 + 8) * H + c0 + 8);
            half2 p0 = __floats2half2_rn(x0.x, x0.y); afr[t][kt][0] = *(uint32_t*)&p0;
            half2 p1 = __floats2half2_rn(x1.x, x1.y); afr[t][kt][1] = *(uint32_t*)&p1;
            half2 p2 = __floats2half2_rn(x2.x, x2.y); afr[t][kt][2] = *(uint32_t*)&p2;
            half2 p3 = __floats2half2_rn(x3.x, x3.y); afr[t][kt][3] = *(uint32_t*)&p3;
        }
    }

    if (tid < H) hs[tid] = __float2half_rn(0.f);
    float c = 0.f;                        // live in tid < 128
    bool is_tanh_gate = ((w >> 2) == 2);  // whole warp same gate type
    const float* __restrict__ gxp = d_gx + (size_t)b * L1 * H4;

    // gate rows this thread activates (lane%4==0 only): [d0[0], d0[2], d1[0], d1[2]]
    int rows[4] = { w * 32 + qr, w * 32 + qr + 8, w * 32 + qr + 16, w * 32 + qr + 24 };
    float gxr[4] = {0.f, 0.f, 0.f, 0.f};
    if ((lane & 3) == 0) {
#pragma unroll
        for (int j = 0; j < 4; j++) gxr[j] = gxp[rows[j]];
    }
    __syncthreads();

    for (int step = 0; step < L1; step++) {
        // B fragments from hs (h replicated across all 8 N-columns)
        uint32_t bfr[8][2];
#pragma unroll
        for (int kt = 0; kt < 8; kt++) {
            bfr[kt][0] = *(const uint32_t*)&hs[kt * 16 + qc];
            bfr[kt][1] = *(const uint32_t*)&hs[kt * 16 + qc + 8];
        }

        // prefetch next step's gx while HMMA runs
        float ngx[4] = {0.f, 0.f, 0.f, 0.f};
        if ((lane & 3) == 0 && step + 1 < L1) {
            const float* gq = gxp + (size_t)(step + 1) * H4;
#pragma unroll
            for (int j = 0; j < 4; j++) ngx[j] = gq[rows[j]];
        }

        float d0[4] = {0.f, 0.f, 0.f, 0.f};
        float d1[4] = {0.f, 0.f, 0.f, 0.f};
#pragma unroll
        for (int kt = 0; kt < 8; kt++) {
            mma16816(d0, afr[0][kt], bfr[kt]);
            mma16816(d1, afr[1][kt], bfr[kt]);
        }

        if ((lane & 3) == 0) {
            float p[4] = { d0[0] + gxr[0], d0[2] + gxr[1], d1[0] + gxr[2], d1[2] + gxr[3] };
#pragma unroll
            for (int j = 0; j < 4; j++)
                gs[rows[j]] = is_tanh_gate ? tanh_acc(p[j]) : sigmoid_acc(p[j]);
        }
        __syncthreads();

        if (tid < H) {
            float gi = gs[tid], gf = gs[tid + H], gg = gs[tid + 2 * H], go = gs[tid + 3 * H];
            c = gf * c + gi * gg;
            float hn = go * tanh_acc(c);
            hs[tid] = __float2half_rn(hn);
            out[(size_t)((b * L1) + step) * H + tid] = hn;
        }
        gxr[0] = ngx[0]; gxr[1] = ngx[1]; gxr[2] = ngx[2]; gxr[3] = ngx[3];
        __syncthreads();
    }
}

// ============================================================
extern "C" void kernel_launch(void* const* d_in, const int* in_sizes, int n_in,
                              void* d_out, int out_size)
{
    const float*         x     = (const float*)d_in[0];
    const unsigned char* xmask = (const unsigned char*)d_in[1];
    const float*         y     = (const float*)d_in[2];
    const unsigned char* ymask = (const unsigned char*)d_in[3];
    const float* Wq_w  = (const float*)d_in[4];
    const float* Wq_b  = (const float*)d_in[5];
    const float* Wup_w = (const float*)d_in[6];
    const float* Wup_b = (const float*)d_in[7];
    // d_in[8] = Wvp_w (multiplied by zeros in reference -> unused)
    const float* Wvp_b = (const float*)d_in[9];
    const float* V_w   = (const float*)d_in[10];
    const float* V_b   = (const float*)d_in[11];
    const float* Wg_w  = (const float*)d_in[12];
    const float* Wg_b  = (const float*)d_in[13];
    const float* W_ih  = (const float*)d_in[14];
    const float* W_hh  = (const float*)d_in[15];
    const float* b_ih  = (const float*)d_in[16];
    const float* b_hh  = (const float*)d_in[17];
    float* out = (float*)d_out;

    k_proj  <<<B * L1 + B * L2, 128>>>(x, y, Wup_w, Wup_b, Wq_w, Wq_b, Wvp_b);
    k_scores<<<dim3(L2 / 32, L1 / 32, B), dim3(32, 8)>>>(xmask, ymask, V_w, V_b);
    k_softmax<<<B * L1, 128>>>();
    k_ctx   <<<dim3(L1 / 16, B), 256>>>(y);
    k_gates <<<(B * L1) / 32, 256>>>(x, Wg_w, Wg_b, W_ih, b_ih, b_hh);
    k_lstm  <<<B, 512>>>(W_hh, out);
}

// round 13
// speedup vs baseline: 1.1353x; 1.1353x over previous
#include <cuda_runtime.h>
#include <cuda_fp16.h>
#include <math.h>
#include <stdint.h>

#define B 8
#define L1 384
#define L2 384
#define H 128
#define H2 256
#define H4 512

// ---- scratch (allocation-free: __device__ globals) ----
__device__ float d_xp[B * L1 * H];
__device__ float d_yp[B * L2 * H];
__device__ float d_s [B * L1 * L2];
__device__ float d_ct[B * L1 * H];
__device__ float d_gx[B * L1 * H4];

__device__ __forceinline__ float tanh_fast(float x) {
    float y;
    asm("tanh.approx.f32 %0, %1;" : "=f"(y) : "f"(x));
    return y;
}
__device__ __forceinline__ float sigmoid_acc(float x) {
    x = fminf(fmaxf(x, -30.f), 30.f);
    return 1.f / (1.f + __expf(-x));
}
__device__ __forceinline__ float tanh_acc(float x) {
    x = fminf(fmaxf(x, -15.f), 15.f);
    float e = __expf(-2.f * x);
    return (1.f - e) / (1.f + e);
}

// ============================================================
// Kernel A: row projections
// ============================================================
__global__ void k_proj(const float* __restrict__ x, const float* __restrict__ y,
                       const float* __restrict__ Wup, const float* __restrict__ bup,
                       const float* __restrict__ Wq,  const float* __restrict__ bq,
                       const float* __restrict__ bvp)
{
    int row = blockIdx.x;
    int o   = threadIdx.x;
    __shared__ float4 in4[H / 4];

    const float* in; const float* W; float bias; float* out;
    if (row < B * L1) {
        in = x + (size_t)row * H;  W = Wup;  bias = bup[o];           out = d_xp + (size_t)row * H;
    } else {
        int r = row - B * L1;
        in = y + (size_t)r * H;    W = Wq;   bias = bq[o] + bvp[o];   out = d_yp + (size_t)r * H;
    }
    if (o < H / 4) in4[o] = ((const float4*)in)[o];
    __syncthreads();

    const float4* W4 = (const float4*)(W + (size_t)o * H);
    float acc = bias;
#pragma unroll
    for (int k = 0; k < H / 4; k++) {
        float4 w = W4[k];
        float4 v = in4[k];
        acc += w.x * v.x + w.y * v.y + w.z * v.z + w.w * v.w;
    }
    out[o] = acc;
}

// ============================================================
// Kernel B: additive attention scores (MUFU-bound)
// ============================================================
__global__ void k_scores(const unsigned char* __restrict__ xmask,
                         const unsigned char* __restrict__ ymask,
                         const float* __restrict__ Vw, const float* __restrict__ Vb)
{
    int b  = blockIdx.z;
    int t0 = blockIdx.y * 32;
    int j0 = blockIdx.x * 32;

    __shared__ float4 xs[32 * 32];
    __shared__ float4 ys[32 * 33];
    __shared__ float4 vs[32];

    int tid = threadIdx.y * 32 + threadIdx.x;
    for (int i = tid; i < 32 * 32; i += 256) {
        int r = i >> 5, k = i & 31;
        xs[r * 32 + k] = ((const float4*)(d_xp + (size_t)((b * L1) + t0 + r) * H))[k];
        ys[r * 33 + k] = ((const float4*)(d_yp + (size_t)((b * L2) + j0 + r) * H))[k];
    }
    if (tid < 32) vs[tid] = ((const float4*)Vw)[tid];
    __syncthreads();

    int j = threadIdx.x;
    float acc[4] = {0.f, 0.f, 0.f, 0.f};

#pragma unroll 4
    for (int k = 0; k < 32; k++) {
        float4 yv = ys[j * 33 + k];
        float4 v  = vs[k];
#pragma unroll
        for (int i = 0; i < 4; i++) {
            float4 xv = xs[(threadIdx.y + i * 8) * 32 + k];
            acc[i] += v.x * tanh_fast(xv.x + yv.x);
            acc[i] += v.y * tanh_fast(xv.y + yv.y);
            acc[i] += v.z * tanh_fast(xv.z + yv.z);
            acc[i] += v.w * tanh_fast(xv.w + yv.w);
        }
    }

    bool  ymb = ymask[b * L2 + j0 + j] != 0;
    float ymv = ymb ? 0.f : 1.f;
    float vb  = Vb[0];
    const float NEG_INF = __int_as_float(0xff800000);
#pragma unroll
    for (int i = 0; i < 4; i++) {
        int t   = t0 + threadIdx.y + i * 8;
        float xm = (xmask[b * L1 + t] != 0) ? 0.f : 1.f;
        float s  = (acc[i] + vb) * (xm * ymv);
        if (ymb) s = NEG_INF;
        d_s[(size_t)((b * L1) + t) * L2 + j0 + j] = s;
    }
}

// ============================================================
// Kernel C: softmax over j
// ============================================================
__global__ void k_softmax()
{
    int row = blockIdx.x;
    float* s = d_s + (size_t)row * L2;
    int tid = threadIdx.x;   // 128

    float v[3];
    float m = -INFINITY;
#pragma unroll
    for (int i = 0; i < 3; i++) { v[i] = s[tid + i * 128]; m = fmaxf(m, v[i]); }

    __shared__ float red[4];
#pragma unroll
    for (int o = 16; o > 0; o >>= 1) m = fmaxf(m, __shfl_xor_sync(~0u, m, o));
    if ((tid & 31) == 0) red[tid >> 5] = m;
    __syncthreads();
    m = fmaxf(fmaxf(red[0], red[1]), fmaxf(red[2], red[3]));

    float sum = 0.f;
#pragma unroll
    for (int i = 0; i < 3; i++) { v[i] = __expf(v[i] - m); sum += v[i]; }
#pragma unroll
    for (int o = 16; o > 0; o >>= 1) sum += __shfl_xor_sync(~0u, sum, o);
    __shared__ float red2[4];
    if ((tid & 31) == 0) red2[tid >> 5] = sum;
    __syncthreads();
    sum = red2[0] + red2[1] + red2[2] + red2[3];

    float inv = 1.0f / sum;
#pragma unroll
    for (int i = 0; i < 3; i++) s[tid + i * 128] = v[i] * inv;
}

// ============================================================
// Kernel D: ct = alpha @ y. 8 t-rows/block (384 blocks: 2.6/SM for
// latency hiding; was 192 @ occ 16.8%). j streamed in chunks of 32,
// register double-buffered.
// ============================================================
#define NCHUNK (L2 / 32)
__global__ void k_ctx(const float* __restrict__ y)
{
    int b  = blockIdx.y;
    int t0 = blockIdx.x * 8;
    __shared__ __align__(16) float ysm[32 * 128];
    __shared__ float alph[8 * 32];

    int tid = threadIdx.x;       // 256
    int h   = tid & 127;
    int tg  = tid >> 7;          // 0..1 -> owns 4 t's
    float acc[4] = {0.f, 0.f, 0.f, 0.f};

    const float4* y4 = (const float4*)(y + (size_t)b * L2 * H);
    const float*  sp = d_s + (size_t)(b * L1 + t0) * L2;

    float4 ybuf[4];
    float  abuf;
#pragma unroll
    for (int q = 0; q < 4; q++) ybuf[q] = y4[tid + 256 * q];
    abuf = sp[(size_t)(tid >> 5) * L2 + (tid & 31)];

    for (int c = 0; c < NCHUNK; c++) {
        __syncthreads();
#pragma unroll
        for (int q = 0; q < 4; q++) ((float4*)ysm)[tid + 256 * q] = ybuf[q];
        alph[tid] = abuf;   // only first 256 slots used (8x32)
        __syncthreads();

        if (c + 1 < NCHUNK) {
#pragma unroll
            for (int q = 0; q < 4; q++) ybuf[q] = y4[(c + 1) * 1024 + tid + 256 * q];
            abuf = sp[(size_t)(tid >> 5) * L2 + (c + 1) * 32 + (tid & 31)];
        }

#pragma unroll 8
        for (int jj = 0; jj < 32; jj++) {
            float yv = ysm[jj * 128 + h];
#pragma unroll
            for (int i = 0; i < 4; i++)
                acc[i] += alph[(tg * 4 + i) * 32 + jj] * yv;
        }
    }
#pragma unroll
    for (int i = 0; i < 4; i++)
        d_ct[(size_t)((b * L1) + t0 + tg * 4 + i) * H + h] = acc[i];
}

// ============================================================
// Kernel E (fused, 16 rows/block -> 192 blocks):
// li = sigmoid([x,ct]@Wg^T+bg)*[x,ct] in SMEM, then
// gx = li @ W_ih^T + (b_ih+b_hh).
// ============================================================
__global__ void k_gates(const float* __restrict__ x,
                        const float* __restrict__ Wg,  const float* __restrict__ bg,
                        const float* __restrict__ Wih, const float* __restrict__ bih,
                        const float* __restrict__ bhh)
{
    int r0 = blockIdx.x * 16;
    int c  = threadIdx.x;                          // 256
    __shared__ __align__(16) float ms [16 * H2];   // merge tile (16KB)
    __shared__ __align__(16) float lis[16 * H2];   // gated tile (16KB)

    for (int i = c; i < 16 * H2; i += 256) {
        int r = i >> 8, k = i & 255;
        ms[i] = (k < H) ? x[(size_t)(r0 + r) * H + k]
                        : d_ct[(size_t)(r0 + r) * H + (k - H)];
    }
    __syncthreads();

    // phase 2: gate GEMV, one Wg column per thread
    {
        float acc[16];
#pragma unroll
        for (int r = 0; r < 16; r++) acc[r] = 0.f;

        const float4* W4  = (const float4*)(Wg + (size_t)c * H2);
        const float4* ms4 = (const float4*)ms;
        for (int k = 0; k < H2 / 4; k++) {
            float4 w = W4[k];
#pragma unroll
            for (int r = 0; r < 16; r++) {
                float4 m = ms4[r * (H2 / 4) + k];
                acc[r] += w.x * m.x + w.y * m.y + w.z * m.z + w.w * m.w;
            }
        }
        float bias = bg[c];
#pragma unroll
        for (int r = 0; r < 16; r++) {
            float g = 1.0f / (1.0f + __expf(-(acc[r] + bias)));
            lis[r * H2 + c] = g * ms[r * H2 + c];
        }
    }
    __syncthreads();

    // phase 3: gx GEMM, thread owns W_ih columns c and c+256
    {
        float acc0[16], acc1[16];
#pragma unroll
        for (int r = 0; r < 16; r++) { acc0[r] = 0.f; acc1[r] = 0.f; }

        const float4* Wa  = (const float4*)(Wih + (size_t)c * H2);
        const float4* Wb  = (const float4*)(Wih + (size_t)(c + 256) * H2);
        const float4* li4 = (const float4*)lis;
        for (int k = 0; k < H2 / 4; k++) {
            float4 wa = Wa[k];
            float4 wb = Wb[k];
#pragma unroll
            for (int r = 0; r < 16; r++) {
                float4 m = li4[r * (H2 / 4) + k];
                acc0[r] += wa.x * m.x + wa.y * m.y + wa.z * m.z + wa.w * m.w;
                acc1[r] += wb.x * m.x + wb.y * m.y + wb.z * m.z + wb.w * m.w;
            }
        }
        float bias0 = bih[c] + bhh[c];
        float bias1 = bih[c + 256] + bhh[c + 256];
#pragma unroll
        for (int r = 0; r < 16; r++) {
            d_gx[(size_t)(r0 + r) * H4 + c]       = acc0[r] + bias0;
            d_gx[(size_t)(r0 + r) * H4 + c + 256] = acc1[r] + bias1;
        }
    }
}

// ============================================================
// Kernel F: LSTM scan (R7 structure — measured best).
// One block per batch, 512 threads = one gate each.
// W_hh loaded+packed to fp16 registers in-kernel (no prep launch).
// h fp16 in SMEM; HFMA2 dot, chunked fp32 promotion; gx prefetch.
// Producer/consumer named barrier: warps 4-15 bar.arrive (non-blocking),
// warps 0-3 bar.sync + cell phase; out[] STG moved off the critical path.
// ============================================================
__global__ void __launch_bounds__(512, 1)
k_lstm(const float* __restrict__ Whh, float* __restrict__ out)
{
    __shared__ __align__(8) __half hs[H];
    __shared__ float gs[H4];

    int b = blockIdx.x;
    int t = threadIdx.x;                    // gate index 0..511

    // One-time: pack this gate's 128 weights into 32 uint2 (fp16x4) regs.
    uint2 wreg[32];
    {
        const float4* wr = (const float4*)(Whh + (size_t)t * H);
#pragma unroll
        for (int kk = 0; kk < 32; kk++) {
            float4 w = wr[kk];
            half2 lo = __floats2half2_rn(w.x, w.y);
            half2 hi = __floats2half2_rn(w.z, w.w);
            wreg[kk].x = *(uint32_t*)&lo;
            wreg[kk].y = *(uint32_t*)&hi;
        }
    }

    if (t < H) hs[t] = __float2half_rn(0.f);
    float c = 0.f;
    const float* __restrict__ gxp = d_gx + (size_t)b * L1 * H4 + t;
    bool is_tanh_gate = ((t >> 7) == 2);

    float gx = gxp[0];
    __syncthreads();
    const uint2* h2p = (const uint2*)hs;

    for (int step = 0; step < L1; step++) {
        float gpre = gx;
        if (step + 1 < L1)
            gx = gxp[(size_t)(step + 1) * H4];   // prefetch next step

        float facc = 0.f;
#pragma unroll
        for (int ch = 0; ch < 4; ch++) {
            __half2 accA = __float2half2_rn(0.f);
            __half2 accB = __float2half2_rn(0.f);
#pragma unroll
            for (int q = 0; q < 8; q++) {
                int kk = ch * 8 + q;
                uint2 hv = h2p[kk];                   // broadcast LDS.64
                accA = __hfma2(*(const __half2*)&wreg[kk].x,
                               *(const __half2*)&hv.x, accA);
                accB = __hfma2(*(const __half2*)&wreg[kk].y,
                               *(const __half2*)&hv.y, accB);
            }
            float2 fa = __half22float2(accA);
            float2 fb = __half22float2(accB);
            facc += (fa.x + fa.y) + (fb.x + fb.y);
        }
        gpre += facc;

        gs[t] = is_tanh_gate ? tanh_acc(gpre) : sigmoid_acc(gpre);

        float hn = 0.f;
        if (t < H) {
            asm volatile("bar.sync 1, 512;" ::: "memory");   // wait for all gs
            float gi = gs[t], gf = gs[t + H], gg = gs[t + 2 * H], go = gs[t + 3 * H];
            c = gf * c + gi * gg;
            hn = go * tanh_acc(c);
            hs[t] = __float2half_rn(hn);
        } else {
            asm volatile("bar.arrive 1, 512;" ::: "memory"); // non-blocking
        }
        __syncthreads();                                     // h ready for all

        if (t < H)
            out[(size_t)((b * L1) + step) * H + t] = hn;     // off critical path
    }
}

// ============================================================
extern "C" void kernel_launch(void* const* d_in, const int* in_sizes, int n_in,
                              void* d_out, int out_size)
{
    const float*         x     = (const float*)d_in[0];
    const unsigned char* xmask = (const unsigned char*)d_in[1];
    const float*         y     = (const float*)d_in[2];
    const unsigned char* ymask = (const unsigned char*)d_in[3];
    const float* Wq_w  = (const float*)d_in[4];
    const float* Wq_b  = (const float*)d_in[5];
    const float* Wup_w = (const float*)d_in[6];
    const float* Wup_b = (const float*)d_in[7];
    // d_in[8] = Wvp_w (multiplied by zeros in reference -> unused)
    const float* Wvp_b = (const float*)d_in[9];
    const float* V_w   = (const float*)d_in[10];
    const float* V_b   = (const float*)d_in[11];
    const float* Wg_w  = (const float*)d_in[12];
    const float* Wg_b  = (const float*)d_in[13];
    const float* W_ih  = (const float*)d_in[14];
    const float* W_hh  = (const float*)d_in[15];
    const float* b_ih  = (const float*)d_in[16];
    const float* b_hh  = (const float*)d_in[17];
    float* out = (float*)d_out;

    k_proj  <<<B * L1 + B * L2, 128>>>(x, y, Wup_w, Wup_b, Wq_w, Wq_b, Wvp_b);
    k_scores<<<dim3(L2 / 32, L1 / 32, B), dim3(32, 8)>>>(xmask, ymask, V_w, V_b);
    k_softmax<<<B * L1, 128>>>();
    k_ctx   <<<dim3(L1 / 8, B), 256>>>(y);
    k_gates <<<(B * L1) / 16, 256>>>(x, Wg_w, Wg_b, W_ih, b_ih, b_hh);
    k_lstm  <<<B, 512>>>(W_hh, out);
}

// round 14
// speedup vs baseline: 1.2116x; 1.0672x over previous
#include <cuda_runtime.h>
#include <cuda_fp16.h>
#include <math.h>
#include <stdint.h>

#define B 8
#define L1 384
#define L2 384
#define H 128
#define H2 256
#define H4 512
#define NFLAGS 192   // 24 t-chunks x 8 batches

// ---- scratch (allocation-free: __device__ globals) ----
__device__ float d_xp[B * L1 * H];
__device__ float d_yp[B * L2 * H];
__device__ float d_s [B * L1 * L2];
__device__ float d_gx[B * L1 * H4];
__device__ int   d_flags[NFLAGS];

__device__ __forceinline__ float tanh_fast(float x) {
    float y;
    asm("tanh.approx.f32 %0, %1;" : "=f"(y) : "f"(x));
    return y;
}
__device__ __forceinline__ float sigmoid_acc(float x) {
    x = fminf(fmaxf(x, -30.f), 30.f);
    return 1.f / (1.f + __expf(-x));
}
__device__ __forceinline__ float tanh_acc(float x) {
    x = fminf(fmaxf(x, -15.f), 15.f);
    float e = __expf(-2.f * x);
    return (1.f - e) / (1.f + e);
}

// ============================================================
// Kernel A: row projections (+ flag reset, stream-ordered before fused)
// ============================================================
__global__ void k_proj(const float* __restrict__ x, const float* __restrict__ y,
                       const float* __restrict__ Wup, const float* __restrict__ bup,
                       const float* __restrict__ Wq,  const float* __restrict__ bq,
                       const float* __restrict__ bvp)
{
    int row = blockIdx.x;
    int o   = threadIdx.x;

    // reset pipeline flags for this replay (blocks 0-1)
    if (row == 0 && o < 128)            d_flags[o] = 0;
    if (row == 1 && o < NFLAGS - 128)   d_flags[128 + o] = 0;

    __shared__ float4 in4[H / 4];
    const float* in; const float* W; float bias; float* out;
    if (row < B * L1) {
        in = x + (size_t)row * H;  W = Wup;  bias = bup[o];           out = d_xp + (size_t)row * H;
    } else {
        int r = row - B * L1;
        in = y + (size_t)r * H;    W = Wq;   bias = bq[o] + bvp[o];   out = d_yp + (size_t)r * H;
    }
    if (o < H / 4) in4[o] = ((const float4*)in)[o];
    __syncthreads();

    const float4* W4 = (const float4*)(W + (size_t)o * H);
    float acc = bias;
#pragma unroll
    for (int k = 0; k < H / 4; k++) {
        float4 w = W4[k];
        float4 v = in4[k];
        acc += w.x * v.x + w.y * v.y + w.z * v.z + w.w * v.w;
    }
    out[o] = acc;
}

// ============================================================
// Kernel B: additive attention scores (MUFU-bound)
// ============================================================
__global__ void k_scores(const unsigned char* __restrict__ xmask,
                         const unsigned char* __restrict__ ymask,
                         const float* __restrict__ Vw, const float* __restrict__ Vb)
{
    int b  = blockIdx.z;
    int t0 = blockIdx.y * 32;
    int j0 = blockIdx.x * 32;

    __shared__ float4 xs[32 * 32];
    __shared__ float4 ys[32 * 33];
    __shared__ float4 vs[32];

    int tid = threadIdx.y * 32 + threadIdx.x;
    for (int i = tid; i < 32 * 32; i += 256) {
        int r = i >> 5, k = i & 31;
        xs[r * 32 + k] = ((const float4*)(d_xp + (size_t)((b * L1) + t0 + r) * H))[k];
        ys[r * 33 + k] = ((const float4*)(d_yp + (size_t)((b * L2) + j0 + r) * H))[k];
    }
    if (tid < 32) vs[tid] = ((const float4*)Vw)[tid];
    __syncthreads();

    int j = threadIdx.x;
    float acc[4] = {0.f, 0.f, 0.f, 0.f};

#pragma unroll 4
    for (int k = 0; k < 32; k++) {
        float4 yv = ys[j * 33 + k];
        float4 v  = vs[k];
#pragma unroll
        for (int i = 0; i < 4; i++) {
            float4 xv = xs[(threadIdx.y + i * 8) * 32 + k];
            acc[i] += v.x * tanh_fast(xv.x + yv.x);
            acc[i] += v.y * tanh_fast(xv.y + yv.y);
            acc[i] += v.z * tanh_fast(xv.z + yv.z);
            acc[i] += v.w * tanh_fast(xv.w + yv.w);
        }
    }

    bool  ymb = ymask[b * L2 + j0 + j] != 0;
    float ymv = ymb ? 0.f : 1.f;
    float vb  = Vb[0];
    const float NEG_INF = __int_as_float(0xff800000);
#pragma unroll
    for (int i = 0; i < 4; i++) {
        int t   = t0 + threadIdx.y + i * 8;
        float xm = (xmask[b * L1 + t] != 0) ? 0.f : 1.f;
        float s  = (acc[i] + vb) * (xm * ymv);
        if (ymb) s = NEG_INF;
        d_s[(size_t)((b * L1) + t) * L2 + j0 + j] = s;
    }
}

// ============================================================
// Kernel C: softmax over j
// ============================================================
__global__ void k_softmax()
{
    int row = blockIdx.x;
    float* s = d_s + (size_t)row * L2;
    int tid = threadIdx.x;   // 128

    float v[3];
    float m = -INFINITY;
#pragma unroll
    for (int i = 0; i < 3; i++) { v[i] = s[tid + i * 128]; m = fmaxf(m, v[i]); }

    __shared__ float red[4];
#pragma unroll
    for (int o = 16; o > 0; o >>= 1) m = fmaxf(m, __shfl_xor_sync(~0u, m, o));
    if ((tid & 31) == 0) red[tid >> 5] = m;
    __syncthreads();
    m = fmaxf(fmaxf(red[0], red[1]), fmaxf(red[2], red[3]));

    float sum = 0.f;
#pragma unroll
    for (int i = 0; i < 3; i++) { v[i] = __expf(v[i] - m); sum += v[i]; }
#pragma unroll
    for (int o = 16; o > 0; o >>= 1) sum += __shfl_xor_sync(~0u, sum, o);
    __shared__ float red2[4];
    if ((tid & 31) == 0) red2[tid >> 5] = sum;
    __syncthreads();
    sum = red2[0] + red2[1] + red2[2] + red2[3];

    float inv = 1.0f / sum;
#pragma unroll
    for (int i = 0; i < 3; i++) s[tid + i * 128] = v[i] * inv;
}

// ============================================================
// Kernel FUSED: producer/consumer pipeline.
// blocks 0..7   : LSTM (one batch each), consumes d_gx chunk-by-chunk.
// blocks 8..103 : workers; 16-row (b,t)-chunks in t-order
//                 (chunk c = tc*8+b; worker w does c=w then c=w+96):
//                 ctx (smem-only) -> merge -> gate -> gx -> release flag.
// All 104 blocks resident (<=148 SMs); workers never wait -> no deadlock.
// ============================================================
__global__ void __launch_bounds__(512, 1)
k_fused(const float* __restrict__ x, const float* __restrict__ y,
        const float* __restrict__ Wg,  const float* __restrict__ bg,
        const float* __restrict__ Wih, const float* __restrict__ bih,
        const float* __restrict__ bhh,
        const float* __restrict__ Whh, float* __restrict__ out)
{
    __shared__ __align__(16) unsigned char sbuf[41984];
    int tid = threadIdx.x;

    if (blockIdx.x < 8) {
        // =============== LSTM consumer (R7 core + chunk polling) ===============
        __half* hs = (__half*)sbuf;                // 256B
        float*  gs = (float*)(sbuf + 256);         // 2KB
        int b = blockIdx.x;
        int t = tid;

        // one-time: pack this gate's 128 W_hh weights into 32 uint2 regs
        uint2 wreg[32];
        {
            const float4* wr = (const float4*)(Whh + (size_t)t * H);
#pragma unroll
            for (int kk = 0; kk < 32; kk++) {
                float4 w = wr[kk];
                half2 lo = __floats2half2_rn(w.x, w.y);
                half2 hi = __floats2half2_rn(w.z, w.w);
                wreg[kk].x = *(uint32_t*)&lo;
                wreg[kk].y = *(uint32_t*)&hi;
            }
        }

        if (t < H) hs[t] = __float2half_rn(0.f);
        float c = 0.f;
        const float* __restrict__ gxp = d_gx + (size_t)b * L1 * H4 + t;
        bool is_tanh_gate = ((t >> 7) == 2);
        __syncthreads();
        const uint2* h2p = (const uint2*)hs;

        float gx = 0.f;
        for (int step = 0; step < L1; step++) {
            if ((step & 15) == 0) {
                if (t == 0) {
                    const int* fp = &d_flags[(step >> 4) * 8 + b];
                    int v;
                    do {
                        asm volatile("ld.acquire.gpu.global.b32 %0, [%1];"
                                     : "=r"(v) : "l"(fp) : "memory");
                    } while (v == 0);
                }
                __syncthreads();
                gx = gxp[(size_t)step * H4];
            }
            float gpre = gx;
            if ((step & 15) != 15)
                gx = gxp[(size_t)(step + 1) * H4];   // prefetch (stays in chunk)

            float facc = 0.f;
#pragma unroll
            for (int ch = 0; ch < 4; ch++) {
                __half2 accA = __float2half2_rn(0.f);
                __half2 accB = __float2half2_rn(0.f);
#pragma unroll
                for (int q = 0; q < 8; q++) {
                    int kk = ch * 8 + q;
                    uint2 hv = h2p[kk];
                    accA = __hfma2(*(const __half2*)&wreg[kk].x,
                                   *(const __half2*)&hv.x, accA);
                    accB = __hfma2(*(const __half2*)&wreg[kk].y,
                                   *(const __half2*)&hv.y, accB);
                }
                float2 fa = __half22float2(accA);
                float2 fb = __half22float2(accB);
                facc += (fa.x + fa.y) + (fb.x + fb.y);
            }
            gpre += facc;

            gs[t] = is_tanh_gate ? tanh_acc(gpre) : sigmoid_acc(gpre);
            __syncthreads();

            if (t < H) {
                float gi = gs[t], gf = gs[t + H], gg = gs[t + 2 * H], go = gs[t + 3 * H];
                c = gf * c + gi * gg;
                float hn = go * tanh_acc(c);
                hs[t] = __float2half_rn(hn);
                out[(size_t)((b * L1) + step) * H + t] = hn;
            }
            __syncthreads();
        }
        return;
    }

    // =============== worker producer ===============
    float* ysm  = (float*)sbuf;                    // 16 j x 128 h  (8KB)
    float* alph = (float*)(sbuf + 8192);           // 16 r x 16 j   (1KB)
    float* ms   = (float*)(sbuf + 9216);           // 16 r x 256    (16KB)
    float* lis  = (float*)(sbuf + 9216 + 16384);   // 16 r x 256    (16KB)

    int w = blockIdx.x - 8;                        // 0..95
    for (int half = 0; half < 2; half++) {
        int cidx = w + half * 96;                  // chunk, t-ordered
        int tc = cidx >> 3;
        int b  = cidx & 7;
        int t0 = tc * 16;

        // ---- ctx: acc[4] over 24 chunks of 16 j ----
        int h  = tid & 127;
        int tg = tid >> 7;                         // 0..3 -> 4 rows each
        float acc[4] = {0.f, 0.f, 0.f, 0.f};

        const float4* y4 = (const float4*)(y + (size_t)b * L2 * H);
        const float*  sp = d_s + (size_t)(b * L1 + t0) * L2;

        float4 ybuf = y4[tid];
        float  abuf = (tid < 256) ? sp[(size_t)(tid >> 4) * L2 + (tid & 15)] : 0.f;

        for (int cj = 0; cj < 24; cj++) {
            __syncthreads();
            ((float4*)ysm)[tid] = ybuf;
            if (tid < 256) alph[tid] = abuf;
            __syncthreads();

            if (cj + 1 < 24) {
                ybuf = y4[(cj + 1) * 512 + tid];
                if (tid < 256)
                    abuf = sp[(size_t)(tid >> 4) * L2 + (cj + 1) * 16 + (tid & 15)];
            }

#pragma unroll 8
            for (int jj = 0; jj < 16; jj++) {
                float yv = ysm[jj * 128 + h];
#pragma unroll
                for (int i = 0; i < 4; i++)
                    acc[i] += alph[(tg * 4 + i) * 16 + jj] * yv;
            }
        }
        __syncthreads();

        // ---- merge tile: x cols [0,128), ct cols [128,256) ----
#pragma unroll
        for (int i = 0; i < 4; i++)
            ms[(tg * 4 + i) * 256 + 128 + h] = acc[i];
        for (int i = tid; i < 16 * 128; i += 512) {
            int r = i >> 7, k = i & 127;
            ms[r * 256 + k] = x[(size_t)(b * L1 + t0 + r) * H + k];
        }
        __syncthreads();

        // ---- gate: lis = sigmoid(ms @ Wg^T + bg) * ms ----
        {
            int rg = tid >> 8;                     // 0..1 -> 8 rows each
            int cc = tid & 255;
            float a8[8];
#pragma unroll
            for (int r = 0; r < 8; r++) a8[r] = 0.f;

            const float4* W4  = (const float4*)(Wg + (size_t)cc * H2);
            const float4* ms4 = (const float4*)ms;
            for (int k = 0; k < H2 / 4; k++) {
                float4 wv = W4[k];
#pragma unroll
                for (int r = 0; r < 8; r++) {
                    float4 m = ms4[(rg * 8 + r) * (H2 / 4) + k];
                    a8[r] += wv.x * m.x + wv.y * m.y + wv.z * m.z + wv.w * m.w;
                }
            }
            float bias = bg[cc];
#pragma unroll
            for (int r = 0; r < 8; r++) {
                float g = 1.0f / (1.0f + __expf(-(a8[r] + bias)));
                lis[(rg * 8 + r) * 256 + cc] = g * ms[(rg * 8 + r) * 256 + cc];
            }
        }
        __syncthreads();

        // ---- gx = lis @ W_ih^T + (b_ih + b_hh), one col per thread ----
        {
            int col = tid;                         // 0..511
            float a16[16];
#pragma unroll
            for (int r = 0; r < 16; r++) a16[r] = 0.f;

            const float4* Wv  = (const float4*)(Wih + (size_t)col * H2);
            const float4* li4 = (const float4*)lis;
            for (int k = 0; k < H2 / 4; k++) {
                float4 wv = Wv[k];
#pragma unroll
                for (int r = 0; r < 16; r++) {
                    float4 m = li4[r * (H2 / 4) + k];
                    a16[r] += wv.x * m.x + wv.y * m.y + wv.z * m.z + wv.w * m.w;
                }
            }
            float bias = bih[col] + bhh[col];
#pragma unroll
            for (int r = 0; r < 16; r++)
                d_gx[(size_t)(b * L1 + t0 + r) * H4 + col] = a16[r] + bias;
        }
        __syncthreads();

        if (tid == 0) {
            asm volatile("st.release.gpu.global.b32 [%0], %1;"
                         :: "l"(&d_flags[cidx]), "r"(1) : "memory");
        }
        __syncthreads();
    }
}

// ============================================================
extern "C" void kernel_launch(void* const* d_in, const int* in_sizes, int n_in,
                              void* d_out, int out_size)
{
    const float*         x     = (const float*)d_in[0];
    const unsigned char* xmask = (const unsigned char*)d_in[1];
    const float*         y     = (const float*)d_in[2];
    const unsigned char* ymask = (const unsigned char*)d_in[3];
    const float* Wq_w  = (const float*)d_in[4];
    const float* Wq_b  = (const float*)d_in[5];
    const float* Wup_w = (const float*)d_in[6];
    const float* Wup_b = (const float*)d_in[7];
    // d_in[8] = Wvp_w (multiplied by zeros in reference -> unused)
    const float* Wvp_b = (const float*)d_in[9];
    const float* V_w   = (const float*)d_in[10];
    const float* V_b   = (const float*)d_in[11];
    const float* Wg_w  = (const float*)d_in[12];
    const float* Wg_b  = (const float*)d_in[13];
    const float* W_ih  = (const float*)d_in[14];
    const float* W_hh  = (const float*)d_in[15];
    const float* b_ih  = (const float*)d_in[16];
    const float* b_hh  = (const float*)d_in[17];
    float* out = (float*)d_out;

    k_proj  <<<B * L1 + B * L2, 128>>>(x, y, Wup_w, Wup_b, Wq_w, Wq_b, Wvp_b);
    k_scores<<<dim3(L2 / 32, L1 / 32, B), dim3(32, 8)>>>(xmask, ymask, V_w, V_b);
    k_softmax<<<B * L1, 128>>>();
    k_fused <<<104, 512>>>(x, y, Wg_w, Wg_b, W_ih, b_ih, b_hh, W_hh, out);
}